// round 17
// baseline (speedup 1.0000x reference)
#include <cuda_runtime.h>
#include <cuda_fp16.h>
#include <math.h>
#include <cstdint>

#define B_SZ   2
#define LSEQ   1024
#define DMODEL 1024
#define DIN    2048
#define NST    16
#define DTR    64
#define MROWS  (B_SZ*LSEQ)   /* 2048 */

// ---------------- scratch (device globals; no allocation allowed) ------------
__device__ __half g_XZ[MROWS*8192];             // fp16 [m][dir*4096 + (xi | z)]
__device__ __half g_Uq[MROWS*4096];             // fp16 u (x_dbl A + scan)
__device__ __half g_Xh[MROWS*DMODEL];           // fp16 (in-proj A)
__device__ __half g_Win[8192*DMODEL];           // fp16 (in-proj B)
__device__ __half g_Xp[256*DIN];                // fp16 padded xpW (x_dbl B)
__device__ float g_XDBLP[8*MROWS*256];
__device__ float g_XDBL[MROWS*256];             // fp32 B/C for scan
__device__ __half g_XDq[MROWS*256];             // fp16 (delta A)
__device__ __half g_dtW[4096*DTR];              // fp16 dir-concat rows (delta B)
__device__ __half g_DELTA[MROWS*4096];          // fp16 delta
__device__ __half g_YGh[MROWS*4096];            // fp16 (out-proj A)
__device__ __half g_Wout[DMODEL*4096];          // fp16 (out-proj B)
__device__ float g_OUTP[4*MROWS*DMODEL];        // out-proj split-K=4 partials

// ======================= helpers =============================================
__device__ __forceinline__ uint32_t smem_u32(const void* p) {
    uint32_t a;
    asm("{ .reg .u64 t; cvta.to.shared.u64 t, %1; cvt.u32.u64 %0, t; }" : "=r"(a) : "l"(p));
    return a;
}
#define LDM4(r0,r1,r2,r3,addr)                                                      \
    asm volatile("ldmatrix.sync.aligned.m8n8.x4.shared.b16 {%0,%1,%2,%3}, [%4];"    \
        : "=r"(r0),"=r"(r1),"=r"(r2),"=r"(r3) : "r"(addr))
#define MMA_F16(c,a,b)                                                              \
    asm volatile("mma.sync.aligned.m16n8k16.row.col.f32.f16.f16.f32 "               \
        "{%0,%1,%2,%3}, {%4,%5,%6,%7}, {%8,%9}, {%0,%1,%2,%3};"                     \
        : "+f"((c)[0]),"+f"((c)[1]),"+f"((c)[2]),"+f"((c)[3])                       \
        : "r"((a)[0]),"r"((a)[1]),"r"((a)[2]),"r"((a)[3]),"r"((b)[0]),"r"((b)[1]))
#define CPA16(dst, src) asm volatile("cp.async.cg.shared.global [%0], [%1], 16;" :: "r"(dst), "l"(src) : "memory")
#define CPCOMMIT()      asm volatile("cp.async.commit_group;" ::: "memory")
#define CPWAIT0()       asm volatile("cp.async.wait_group 0;" ::: "memory")
#define CPWAIT1()       asm volatile("cp.async.wait_group 1;" ::: "memory")
#define EX2F(r, x)      asm("ex2.approx.f32 %0, %1;" : "=f"(r) : "f"(x))

__device__ __forceinline__ void store_h(__half* __restrict__ p, int i, float4 v) {
    reinterpret_cast<__half2*>(p)[2*i]   = __floats2half2_rn(v.x, v.y);
    reinterpret_cast<__half2*>(p)[2*i+1] = __floats2half2_rn(v.z, v.w);
}

// ======== fp16 single-term GEMM, 3-stage cp.async pipeline ===================
// C[M,N] = A[M,K] * B[N,K]^T.  A += a_off1 when CTA n-tile >= nsplit.
// kz>0: split-K over blockIdx.z (C offset z*M*ldc).
// EPI: 0 = fp32 store, 2 = fp16 store, 3 = softplus(acc+bias) fp16 store.
#define BKC 32
#define ASTRIDE 80
#define H2_A    0
#define H2_B    10240
#define H2_STRIDE 20480
#define H2_SMEM (3*H2_STRIDE)

template<int EPI>
__global__ __launch_bounds__(256, 2) void hgemm2(
    const __half* __restrict__ Ah, int lda, int a_off1, int nsplit,
    const __half* __restrict__ B, int ldb,
    void* __restrict__ Cv, int ldc, int K,
    const float* __restrict__ bias0, const float* __restrict__ bias1, int kz)
{
    extern __shared__ char sm[];
    const uint32_t smb = smem_u32(sm);
    const int tid = threadIdx.x;
    const int bm = blockIdx.y * 128, bn = blockIdx.x * 128;
    float* C = (float*)Cv;
    __half* Ch = (__half*)Cv;
    if (kz > 0) {
        Ah += (size_t)blockIdx.z * kz;
        B  += (size_t)blockIdx.z * kz;
        C  += (size_t)blockIdx.z * (size_t)(gridDim.y * 128) * (size_t)ldc;
        K = kz;
    }
    const int aoff = (nsplit && bn >= nsplit) ? a_off1 : 0;

    const int grow = tid >> 1;
    const int seg  = (tid & 1) << 1;
    const char* gAh = (const char*)(Ah + aoff + (size_t)(bm + grow) * lda);
    const char* gB  = (const char*)(B  + (size_t)(bn + grow) * ldb);
    const uint32_t srow = smb + (uint32_t)(grow * ASTRIDE + seg * 16);

    const int wid = tid >> 5, lane = tid & 31;
    const int wm = (wid >> 2) * 64;
    const int wn = (wid & 3) * 32;
    const int tq = lane >> 2, tr = lane & 3;
    const uint32_t aoffm = (uint32_t)((wm + (lane & 15)) * ASTRIDE + ((lane >> 4) << 4));
    const int g = lane >> 3;
    const uint32_t boffm = (uint32_t)((wn + ((g >> 1) << 3) + (lane & 7)) * ASTRIDE + ((g & 1) << 4));

    float acc[4][4][4];
#pragma unroll
    for (int i = 0; i < 4; i++)
#pragma unroll
        for (int j = 0; j < 4; j++)
#pragma unroll
            for (int q = 0; q < 4; q++) acc[i][j][q] = 0.f;

    const int nch = K / BKC;

    auto issue = [&](int s) {
        const uint32_t st = srow + (uint32_t)(s % 3) * H2_STRIDE;
        const int go = s * (BKC * 2) + seg * 16;
        CPA16(st + H2_A,      gAh + go);
        CPA16(st + H2_A + 16, gAh + go + 16);
        CPA16(st + H2_B,      gB + go);
        CPA16(st + H2_B + 16, gB + go + 16);
        CPCOMMIT();
    };

    issue(0);
    if (nch > 1) issue(1);
    for (int s = 0; s < nch; s++) {
        if (s + 1 < nch) CPWAIT1();
        else             CPWAIT0();
        __syncthreads();
        if (s + 2 < nch) issue(s + 2);
        const uint32_t sa = smb + (uint32_t)(s % 3) * H2_STRIDE;
#pragma unroll
        for (int ph = 0; ph < 2; ph++) {
            const uint32_t ka = sa + ph * 32;
            uint32_t ah[4][4], bb[4][2];
#pragma unroll
            for (int i = 0; i < 4; i++)
                LDM4(ah[i][0], ah[i][1], ah[i][2], ah[i][3], ka + H2_A + aoffm + i*(16*ASTRIDE));
            LDM4(bb[0][0], bb[0][1], bb[1][0], bb[1][1], ka + H2_B + boffm);
            LDM4(bb[2][0], bb[2][1], bb[3][0], bb[3][1], ka + H2_B + boffm + 16*ASTRIDE);
#pragma unroll
            for (int i = 0; i < 4; i++)
#pragma unroll
                for (int j = 0; j < 4; j++)
                    MMA_F16(acc[i][j], ah[i], bb[j]);
        }
    }

    const float* bias = nullptr;
    if (EPI == 3) bias = (nsplit && bn >= nsplit) ? (bias1 - nsplit) : bias0;
#pragma unroll
    for (int i = 0; i < 4; i++) {
        const int row0 = bm + wm + 16*i + tq;
#pragma unroll
        for (int j = 0; j < 4; j++) {
            const int col = bn + wn + 8*j + 2*tr;
            float v0 = acc[i][j][0], v1 = acc[i][j][1];
            float v2 = acc[i][j][2], v3 = acc[i][j][3];
            if (EPI == 3) {
                const float b0v = bias[col], b1v = bias[col+1];
                v0 += b0v; v1 += b1v; v2 += b0v; v3 += b1v;
                v0 = (v0 > 20.f) ? v0 : log1pf(__expf(v0));
                v1 = (v1 > 20.f) ? v1 : log1pf(__expf(v1));
                v2 = (v2 > 20.f) ? v2 : log1pf(__expf(v2));
                v3 = (v3 > 20.f) ? v3 : log1pf(__expf(v3));
            }
            if (EPI == 0) {
                *reinterpret_cast<float2*>(C + (size_t)row0 * ldc + col)       = make_float2(v0, v1);
                *reinterpret_cast<float2*>(C + (size_t)(row0 + 8) * ldc + col) = make_float2(v2, v3);
            } else {
                *reinterpret_cast<__half2*>(Ch + (size_t)row0 * ldc + col)       = __floats2half2_rn(v0, v1);
                *reinterpret_cast<__half2*>(Ch + (size_t)(row0 + 8) * ldc + col) = __floats2half2_rn(v2, v3);
            }
        }
    }
}

// ======================= single merged convert kernel =========================
#define N4_X    (MROWS*DMODEL/4)
#define N4_INW  (4096*DMODEL/4)
#define N4_DTW  (2048*DTR/4)
#define N4_XP   (256*DIN/4)
#define N4_OUT  (DMODEL*4096/4)
#define N4_ALL  (N4_X + 2*N4_INW + 2*N4_DTW + N4_XP + N4_OUT)

__global__ __launch_bounds__(256) void cvt_all_kernel(
    const float* __restrict__ x,
    const float* __restrict__ inW_f, const float* __restrict__ inW_b,
    const float* __restrict__ dtW_f, const float* __restrict__ dtW_b,
    const float* __restrict__ xpW_f, const float* __restrict__ xpW_b,
    const float* __restrict__ outW_f, const float* __restrict__ outW_b)
{
    int i = blockIdx.x * 256 + threadIdx.x;
    if (i < N4_X) {
        store_h(g_Xh, i, reinterpret_cast<const float4*>(x)[i]);
        return;
    }
    i -= N4_X;
    if (i < 2*N4_INW) {
        const float4 v = (i < N4_INW)
            ? reinterpret_cast<const float4*>(inW_f)[i]
            : reinterpret_cast<const float4*>(inW_b)[i - N4_INW];
        store_h(g_Win, i, v);
        return;
    }
    i -= 2*N4_INW;
    if (i < 2*N4_DTW) {
        const float4 v = (i < N4_DTW)
            ? reinterpret_cast<const float4*>(dtW_f)[i]
            : reinterpret_cast<const float4*>(dtW_b)[i - N4_DTW];
        store_h(g_dtW, i, v);
        return;
    }
    i -= 2*N4_DTW;
    if (i < N4_XP) {
        const int idx = i * 4;
        const int r = idx >> 11, c = idx & 2047;
        float4 v = make_float4(0.f,0.f,0.f,0.f);
        if (r < 96)                   v = *reinterpret_cast<const float4*>(xpW_f + r*2048 + c);
        else if (r >= 128 && r < 224) v = *reinterpret_cast<const float4*>(xpW_b + (r-128)*2048 + c);
        store_h(g_Xp, i, v);
        return;
    }
    i -= N4_XP;
    {
        const int idx = i * 4;
        const int r = idx >> 12, c = idx & 4095;
        const float4 v = (c < 2048)
            ? *reinterpret_cast<const float4*>(outW_f + (size_t)r*2048 + c)
            : *reinterpret_cast<const float4*>(outW_b + (size_t)r*2048 + (c - 2048));
        store_h(g_Wout, i, v);
    }
}

__global__ __launch_bounds__(256) void reduce_out_kernel(float* __restrict__ out)
{
    const int i = blockIdx.x * 256 + threadIdx.x;
    float4 s = reinterpret_cast<const float4*>(g_OUTP)[i];
#pragma unroll
    for (int k = 1; k < 4; k++) {
        const float4 p = reinterpret_cast<const float4*>(g_OUTP + (size_t)k*MROWS*DMODEL)[i];
        s.x += p.x; s.y += p.y; s.z += p.z; s.w += p.w;
    }
    reinterpret_cast<float4*>(out)[i] = make_float4(0.5f*s.x, 0.5f*s.y, 0.5f*s.z, 0.5f*s.w);
}

// ------- depthwise conv + SiLU: 4 rows/thread; fp16 in, fp16 out -------------
__global__ __launch_bounds__(256) void conv_silu_kernel(
    const float* __restrict__ convW_f, const float* __restrict__ convB_f,
    const float* __restrict__ convW_b, const float* __restrict__ convB_b)
{
    const int t = blockIdx.x * 256 + threadIdx.x;   // over (MROWS/4)*4096
    const int c = t & 4095;
    const int rq = t >> 12;
    const int b = rq >> 8;
    const int l0 = (rq & 255) << 2;
    const int dir = c >> 11;
    const int d = c & (DIN - 1);
    const float* w = (dir ? convW_b : convW_f) + d*4;
    const float bias = (dir ? convB_b : convB_f)[d];
    const __half* xi = g_XZ + dir*4096 + d;

    float xv[7];
    if (dir == 0) {
#pragma unroll
        for (int k = 0; k < 7; k++) {
            const int ls = l0 - 3 + k;
            xv[k] = (ls >= 0) ? __half2float(xi[(size_t)(b*LSEQ + ls)*8192]) : 0.f;
        }
#pragma unroll
        for (int j = 0; j < 4; j++) {
            float acc = bias;
#pragma unroll
            for (int k = 0; k < 4; k++) acc = fmaf(w[k], xv[j + k], acc);
            const float sig = 1.f / (1.f + __expf(-acc));
            g_Uq[(size_t)(b*LSEQ + l0 + j)*4096 + c] = __float2half(acc * sig);
        }
    } else {
#pragma unroll
        for (int k = 0; k < 7; k++) {
            const int ls = l0 + k;
            xv[k] = (ls < LSEQ) ? __half2float(xi[(size_t)(b*LSEQ + ls)*8192]) : 0.f;
        }
#pragma unroll
        for (int j = 0; j < 4; j++) {
            float acc = bias;
#pragma unroll
            for (int k = 0; k < 4; k++) acc = fmaf(w[k], xv[j + 3 - k], acc);
            const float sig = 1.f / (1.f + __expf(-acc));
            g_Uq[(size_t)(b*LSEQ + l0 + j)*4096 + c] = __float2half(acc * sig);
        }
    }
}

// ------------------ split-K reduce; emits fp32 + fp16 plane ------------------
__global__ __launch_bounds__(256) void reduce_xdbl_kernel()
{
    const int i = blockIdx.x * 256 + threadIdx.x;
    float s = 0.f;
#pragma unroll
    for (int k = 0; k < 8; k++) s += g_XDBLP[(size_t)k*MROWS*256 + i];
    g_XDBL[i] = s;
    g_XDq[i] = __float2half(s);
}

// ------------- selective scan: 2 states/thread, ex2, fp16 inputs -------------
__global__ __launch_bounds__(256) void scan_kernel(
    const float* __restrict__ Alog_f, const float* __restrict__ Alog_b,
    const float* __restrict__ Dp_f,  const float* __restrict__ Dp_b)
{
    const int dir = blockIdx.z;
    const int b   = blockIdx.y;
    const int d0  = blockIdx.x * 32;
    const int t    = threadIdx.x;
    const int lane = t & 31;
    const int w    = t >> 5;
    const int dlw  = (w << 2) + (lane >> 3);
    const int np   = lane & 7;
    const int d    = d0 + dlw;

    const float LOG2E = 1.4426950408889634f;
    const float* Alog = dir ? Alog_b : Alog_f;
    const float Ac0 = -__expf(Alog[d*NST + np])     * LOG2E;
    const float Ac1 = -__expf(Alog[d*NST + np + 8]) * LOG2E;
    const float DpE = (dir ? Dp_b : Dp_f)[d0 + (t & 31)];

    __shared__ float2 sDdw[32][32];
    __shared__ float2 sUZ [32][32];
    __shared__ float4 sBC [32][8];
    __shared__ float  sY  [32][32];

    const int sll = t >> 5;
    const int sdq = t & 31;
    const int bll = t >> 3, bj = t & 7;

    float rgD[4], rgU[4], rgZ[4], rgB[4];
    auto prefetch = [&](int lb) {
#pragma unroll
        for (int e = 0; e < 4; e++) {
            const int row = b*LSEQ + lb + sll + e*8;
            rgD[e] = __half2float(g_DELTA[(size_t)row*4096 + dir*2048 + d0 + sdq]);
            rgU[e] = __half2float(g_Uq[(size_t)row*4096 + dir*2048 + d0 + sdq]);
            rgZ[e] = __half2float(g_XZ[(size_t)row*8192 + dir*4096 + 2048 + d0 + sdq]);
        }
        const int rowb = b*LSEQ + lb + bll;
        rgB[0] = g_XDBL[(size_t)rowb*256 + dir*128 + 64 + bj];
        rgB[1] = g_XDBL[(size_t)rowb*256 + dir*128 + 80 + bj];
        rgB[2] = g_XDBL[(size_t)rowb*256 + dir*128 + 64 + bj + 8];
        rgB[3] = g_XDBL[(size_t)rowb*256 + dir*128 + 80 + bj + 8];
    };

    prefetch((dir == 0) ? 0 : (LSEQ - 32));

    float h0 = 0.f, h1 = 0.f;
    const int NCH = LSEQ / 32;
    for (int c = 0; c < NCH; c++) {
        __syncthreads();
#pragma unroll
        for (int e = 0; e < 4; e++) {
            sDdw[sll + e*8][sdq] = make_float2(rgD[e], rgD[e]*rgU[e]);
            sUZ [sll + e*8][sdq] = make_float2(rgU[e], rgZ[e]);
        }
        sBC[bll][bj] = make_float4(rgB[0], rgB[1], rgB[2], rgB[3]);
        __syncthreads();
        if (c + 1 < NCH)
            prefetch((dir == 0) ? (c+1)*32 : (LSEQ - (c+2)*32));
        const int lb = (dir == 0) ? c*32 : (LSEQ - (c+1)*32);
#pragma unroll 4
        for (int s = 0; s < 32; s++) {
            const int ll = (dir == 0) ? s : (31 - s);
            const float2 ddw = sDdw[ll][dlw];
            const float4 bc  = sBC[ll][np];
            float dA0, dA1;
            EX2F(dA0, ddw.x * Ac0);
            EX2F(dA1, ddw.x * Ac1);
            h0 = fmaf(h0, dA0, ddw.y * bc.x);
            h1 = fmaf(h1, dA1, ddw.y * bc.z);
            float py = fmaf(h1, bc.w, h0 * bc.y);
            py += __shfl_xor_sync(0xffffffffu, py, 4);
            py += __shfl_xor_sync(0xffffffffu, py, 2);
            py += __shfl_xor_sync(0xffffffffu, py, 1);
            if (np == 0) sY[ll][dlw] = py;
        }
        __syncthreads();
#pragma unroll
        for (int e = 0; e < 4; e++) {
            const int ll = sll + e*8;
            const float2 uz = sUZ[ll][sdq];
            const float y = fmaf(uz.x, DpE, sY[ll][sdq]);
            const float sig = 1.f / (1.f + __expf(-uz.y));
            const float yg = y * (uz.y * sig);
            const size_t o = (size_t)(b*LSEQ + lb + ll)*4096 + dir*2048 + d0 + sdq;
            g_YGh[o] = __float2half(yg);
        }
    }
}

// ------------------------------------ launch ---------------------------------
extern "C" void kernel_launch(void* const* d_in, const int* in_sizes, int n_in,
                              void* d_out, int out_size)
{
    const float* x      = (const float*)d_in[0];
    const float* inW_f  = (const float*)d_in[1];
    const float* convW_f= (const float*)d_in[2];
    const float* convB_f= (const float*)d_in[3];
    const float* xpW_f  = (const float*)d_in[4];
    const float* dtW_f  = (const float*)d_in[5];
    const float* dtB_f  = (const float*)d_in[6];
    const float* Alog_f = (const float*)d_in[7];
    const float* Dp_f   = (const float*)d_in[8];
    const float* outW_f = (const float*)d_in[9];
    const float* inW_b  = (const float*)d_in[10];
    const float* convW_b= (const float*)d_in[11];
    const float* convB_b= (const float*)d_in[12];
    const float* xpW_b  = (const float*)d_in[13];
    const float* dtW_b  = (const float*)d_in[14];
    const float* dtB_b  = (const float*)d_in[15];
    const float* Alog_b = (const float*)d_in[16];
    const float* Dp_b   = (const float*)d_in[17];
    const float* outW_b = (const float*)d_in[18];
    float* out = (float*)d_out;

    float *XDBLP, *OUTP;
    __half *XZ, *Xh, *Win, *Uq, *Xp, *XDq, *dtW, *DELTA, *YGh, *Wout;
    cudaGetSymbolAddress((void**)&XZ,    g_XZ);
    cudaGetSymbolAddress((void**)&XDBLP, g_XDBLP);
    cudaGetSymbolAddress((void**)&DELTA, g_DELTA);
    cudaGetSymbolAddress((void**)&OUTP,  g_OUTP);
    cudaGetSymbolAddress((void**)&Xh,    g_Xh);
    cudaGetSymbolAddress((void**)&Win,   g_Win);
    cudaGetSymbolAddress((void**)&Uq,    g_Uq);
    cudaGetSymbolAddress((void**)&Xp,    g_Xp);
    cudaGetSymbolAddress((void**)&XDq,   g_XDq);
    cudaGetSymbolAddress((void**)&dtW,   g_dtW);
    cudaGetSymbolAddress((void**)&YGh,   g_YGh);
    cudaGetSymbolAddress((void**)&Wout,  g_Wout);

    cudaFuncSetAttribute(hgemm2<0>, cudaFuncAttributeMaxDynamicSharedMemorySize, H2_SMEM);
    cudaFuncSetAttribute(hgemm2<2>, cudaFuncAttributeMaxDynamicSharedMemorySize, H2_SMEM);
    cudaFuncSetAttribute(hgemm2<3>, cudaFuncAttributeMaxDynamicSharedMemorySize, H2_SMEM);

    // 0) all operand conversions in one launch
    cvt_all_kernel<<<N4_ALL/256, 256>>>(x, inW_f, inW_b, dtW_f, dtW_b,
                                        xpW_f, xpW_b, outW_f, outW_b);

    // 1) input projection -> fp16 XZ: [2048,8192] = X * Win^T
    hgemm2<2><<<dim3(64,16,1), 256, H2_SMEM>>>(
        Xh, DMODEL, 0, 0, Win, DMODEL, XZ, 8192, DMODEL, nullptr, nullptr, 0);

    // 2) depthwise conv + SiLU (fp16 in/out)
    conv_silu_kernel<<<(MROWS/4*4096)/256, 256>>>(convW_f, convB_f, convW_b, convB_b);

    // 3) x_dbl: [2048,256] = U[dir-slice] * Xp^T, split-K=8 (fp32 partials)
    hgemm2<0><<<dim3(2,16,8), 256, H2_SMEM>>>(
        Uq, 4096, 2048, 128, Xp, DIN, XDBLP, 256, DIN, nullptr, nullptr, 256);
    reduce_xdbl_kernel<<<(MROWS*256)/256, 256>>>();

    // 4) delta = softplus(dt @ dtWcat^T + dtB) -> fp16, N=4096, K=64
    hgemm2<3><<<dim3(32,16,1), 256, H2_SMEM>>>(
        XDq, 256, 128, 2048, dtW, DTR, DELTA, 4096, DTR, dtB_f, dtB_b, 0);

    // 5) selective scan + gating (fp16 inputs)
    scan_kernel<<<dim3(64,2,2), 256>>>(Alog_f, Alog_b, Dp_f, Dp_b);

    // 6) out-proj split-K=4, then 0.5*sum
    hgemm2<0><<<dim3(8,16,4), 256, H2_SMEM>>>(
        YGh, 4096, 0, 0, Wout, 4096, OUTP, DMODEL, 4096, nullptr, nullptr, 1024);
    reduce_out_kernel<<<(MROWS*DMODEL/4)/256, 256>>>(out);
}